// round 1
// baseline (speedup 1.0000x reference)
#include <cuda_runtime.h>
#include <cuda_bf16.h>

// Problem constants (from reference): B=8, C=128, H=W=64, O=128, 3x3, stride 1, pad 1, dil 1
#define BB 8
#define CC 128
#define HH 64
#define WW 64
#define OO 128
#define KTAP 9
#define HW (HH*WW)          // 4096
#define CK (CC*KTAP)        // 1152

// Scratch: channels-last x and transposed weights
__device__ float g_xT[BB*HH*WW*CC];   // [b][h][w][c]  16 MB
__device__ float g_wT[CK*OO];         // [k*C+c][o]    576 KB

// ---------------------------------------------------------------------------
// Kernel 1: x [B,C,H,W] -> xT [B,H,W,C]  (tiled 32x32 transpose per batch)
// grid (HW/32=128, C/32=4, B), block (32,8)
// ---------------------------------------------------------------------------
__global__ void xpose_kernel(const float* __restrict__ x) {
    __shared__ float tile[32][33];
    int b   = blockIdx.z;
    int hw0 = blockIdx.x * 32;
    int c0  = blockIdx.y * 32;
    const float* xb = x + (size_t)b * CC * HW;
#pragma unroll
    for (int j = 0; j < 32; j += 8)
        tile[threadIdx.y + j][threadIdx.x] =
            xb[(size_t)(c0 + threadIdx.y + j) * HW + hw0 + threadIdx.x];
    __syncthreads();
    float* ob = g_xT + (size_t)b * HW * CC;
#pragma unroll
    for (int j = 0; j < 32; j += 8)
        ob[(size_t)(hw0 + threadIdx.y + j) * CC + c0 + threadIdx.x] =
            tile[threadIdx.x][threadIdx.y + j];
}

// ---------------------------------------------------------------------------
// Kernel 2: weight [O,C,3,3] -> wT [k*C+c][O]
// ---------------------------------------------------------------------------
__global__ void wpose_kernel(const float* __restrict__ w) {
    int idx = blockIdx.x * blockDim.x + threadIdx.x;
    if (idx >= CK * OO) return;
    int r = idx >> 7;        // k*C + c
    int o = idx & 127;
    int k = r >> 7;          // r / 128  (C == 128)
    int c = r & 127;
    g_wT[idx] = w[(size_t)o * CK + c * KTAP + k];
}

// ---------------------------------------------------------------------------
// Kernel 3: fused gather + SGEMM
// grid = B * 64 (one block per (b, output row ho)), block = 256 threads
// Output tile: TM=64 spatial (full row) x TN=128 outputs.
// Reduction over r = k*128 + c in KT=32 chunks.
// Thread tile: 4 (m) x 8 (n), threads as 16(ty) x 16(tx).
// ---------------------------------------------------------------------------
__global__ void __launch_bounds__(256, 2) dcn_main_kernel(
    const float* __restrict__ offset,
    const float* __restrict__ bias,
    float* __restrict__ out)
{
    const int b    = blockIdx.x >> 6;
    const int trow = blockIdx.x & 63;     // ho; m == wo
    const int tid  = threadIdx.x;

    __shared__ float sA[32][68];          // [kk(c)][m], padded, 16B-aligned rows
    __shared__ float sB[32][128];         // [kk(c)][o]
    __shared__ int   sIdx[KTAP][64][4];   // corner base indices into g_xT
    __shared__ float sWt[KTAP][64][4];    // corner bilinear weights (0 if OOB)

    // ---- precompute bilinear params for all (m, tap) pairs ----
    for (int p = tid; p < 64 * KTAP; p += 256) {
        int m = p & 63;
        int k = p >> 6;
        int ho = trow, wo = m;
        float dy = offset[(((size_t)b * 18 + 2 * k    ) * 64 + ho) * 64 + wo];
        float dx = offset[(((size_t)b * 18 + 2 * k + 1) * 64 + ho) * 64 + wo];
        float py = (float)(ho - 1 + k / 3) + dy;
        float px = (float)(wo - 1 + k % 3) + dx;
        float y0f = floorf(py), x0f = floorf(px);
        int   y0  = (int)y0f,   x0  = (int)x0f;
        float ly = py - y0f, lx = px - x0f;
        float ww[4] = { (1.f - ly) * (1.f - lx), (1.f - ly) * lx,
                        ly * (1.f - lx),         ly * lx };
#pragma unroll
        for (int i = 0; i < 4; i++) {
            int yy = y0 + (i >> 1);
            int xx = x0 + (i & 1);
            bool v = (yy >= 0) & (yy < HH) & (xx >= 0) & (xx < WW);
            sWt[k][m][i]  = v ? ww[i] : 0.f;
            sIdx[k][m][i] = v ? (((b * HH + yy) * WW + xx) * CC) : 0;
        }
    }

    float acc[4][8];
#pragma unroll
    for (int i = 0; i < 4; i++)
#pragma unroll
        for (int j = 0; j < 8; j++) acc[i][j] = 0.f;

    const int ty  = tid >> 4;   // 0..15, m-group
    const int tx  = tid & 15;   // 0..15, n-group
    const int kkc = tid & 31;   // c within chunk for A-fill
    const int mg  = tid >> 5;   // 0..7 m-group for A-fill (constant per warp)

    for (int r0 = 0; r0 < CK; r0 += 32) {
        const int k  = r0 >> 7;
        const int c0 = r0 & 127;
        __syncthreads();

        // fill B tile: 32x128 floats, coalesced float4 copy
        {
            const float4* src = reinterpret_cast<const float4*>(g_wT + (size_t)r0 * OO);
            float4* dst = reinterpret_cast<float4*>(&sB[0][0]);
#pragma unroll
            for (int i = 0; i < 4; i++) dst[tid + i * 256] = src[tid + i * 256];
        }

        // fill A tile: gather-on-the-fly bilinear, coalesced over channels
#pragma unroll
        for (int i = 0; i < 8; i++) {
            int m = mg * 8 + i;
            const int*   id = sIdx[k][m];
            const float* w4 = sWt[k][m];
            int cc = c0 + kkc;
            float v = w4[0] * g_xT[id[0] + cc]
                    + w4[1] * g_xT[id[1] + cc]
                    + w4[2] * g_xT[id[2] + cc]
                    + w4[3] * g_xT[id[3] + cc];
            sA[kkc][m] = v;
        }
        __syncthreads();

        // compute: outer-product accumulation
#pragma unroll
        for (int kk = 0; kk < 32; kk++) {
            float4 av = *reinterpret_cast<const float4*>(&sA[kk][ty * 4]);
            float4 b0 = *reinterpret_cast<const float4*>(&sB[kk][tx * 8]);
            float4 b1 = *reinterpret_cast<const float4*>(&sB[kk][tx * 8 + 4]);
            float a[4] = { av.x, av.y, av.z, av.w };
            float bq[8] = { b0.x, b0.y, b0.z, b0.w, b1.x, b1.y, b1.z, b1.w };
#pragma unroll
            for (int mm = 0; mm < 4; mm++)
#pragma unroll
                for (int nn = 0; nn < 8; nn++)
                    acc[mm][nn] += a[mm] * bq[nn];
        }
    }

    // epilogue: add bias, vectorized store (4 consecutive wo per thread)
    const int hwb = trow * 64 + ty * 4;
#pragma unroll
    for (int nn = 0; nn < 8; nn++) {
        int n = tx * 8 + nn;
        float bv = bias[n];
        float4 v = make_float4(acc[0][nn] + bv, acc[1][nn] + bv,
                               acc[2][nn] + bv, acc[3][nn] + bv);
        *reinterpret_cast<float4*>(out + ((size_t)(b * OO + n)) * HW + hwb) = v;
    }
}

// ---------------------------------------------------------------------------
extern "C" void kernel_launch(void* const* d_in, const int* in_sizes, int n_in,
                              void* d_out, int out_size)
{
    const float* x      = (const float*)d_in[0];
    const float* offset = (const float*)d_in[1];
    const float* weight = (const float*)d_in[2];
    const float* bias   = (const float*)d_in[3];
    float* out = (float*)d_out;

    dim3 g1(HW / 32, CC / 32, BB), b1(32, 8);
    xpose_kernel<<<g1, b1>>>(x);

    int nw = CK * OO;
    wpose_kernel<<<(nw + 255) / 256, 256>>>(weight);

    dcn_main_kernel<<<BB * 64, 256>>>(offset, bias, out);
}

// round 4
// speedup vs baseline: 2.0678x; 2.0678x over previous
#include <cuda_runtime.h>
#include <cuda_bf16.h>
#include <cstdint>

// Problem constants: B=8, C=128, H=W=64, O=128, 3x3, stride 1, pad 1, dil 1
#define BB 8
#define CC 128
#define HH 64
#define WW 64
#define OO 128
#define KTAP 9
#define HW (HH*WW)          // 4096
#define CK (CC*KTAP)        // 1152
#define NCHUNK 18           // CK / 64

// Scratch
__device__ float g_xT[BB*HH*WW*CC];                  // [b][h][w][c] fp32, 16 MB
__device__ unsigned char g_wbHi[NCHUNK*16384];       // bf16 B chunk tiles (hi) [ch][o][c]
__device__ unsigned char g_wbLo[NCHUNK*16384];       // bf16 B chunk tiles (lo)

// ---------------------------------------------------------------------------
// SMEM layout (dynamic), A/B rows padded to 144 B for conflict-free ldmatrix
// ---------------------------------------------------------------------------
#define AROW 144
#define ATILE (128*AROW)            // 18432
#define A_OFF(st,hl) (((st)*2+(hl))*ATILE)
#define SM_B   (4*ATILE)            // 73728
#define B_OFF(st,hl) (SM_B + ((st)*2+(hl))*ATILE)
#define SM_IDX (8*ATILE)            // 147456, [9][128][4] int
#define SM_WT  (SM_IDX + 9*128*4*4) // 165888, [9][128][4] float
#define SMEM_TOTAL (SM_WT + 9*128*4*4)  // 184320

__device__ __forceinline__ uint32_t smem_u32(const void* p) {
    uint32_t a;
    asm("{ .reg .u64 t; cvta.to.shared.u64 t, %1; cvt.u32.u64 %0, t; }" : "=r"(a) : "l"(p));
    return a;
}
__device__ __forceinline__ void ldsm4(uint32_t addr, uint32_t* r) {
    asm volatile("ldmatrix.sync.aligned.m8n8.x4.shared.b16 {%0,%1,%2,%3}, [%4];"
                 : "=r"(r[0]), "=r"(r[1]), "=r"(r[2]), "=r"(r[3]) : "r"(addr));
}
__device__ __forceinline__ void mma16816(float* d, const uint32_t* a, const uint32_t* b) {
    asm volatile("mma.sync.aligned.m16n8k16.row.col.f32.bf16.bf16.f32 "
                 "{%0,%1,%2,%3}, {%4,%5,%6,%7}, {%8,%9}, {%0,%1,%2,%3};"
                 : "+f"(d[0]), "+f"(d[1]), "+f"(d[2]), "+f"(d[3])
                 : "r"(a[0]), "r"(a[1]), "r"(a[2]), "r"(a[3]), "r"(b[0]), "r"(b[1]));
}
__device__ __forceinline__ void cp16(uint32_t daddr, const void* src) {
    asm volatile("cp.async.cg.shared.global [%0], [%1], 16;" :: "r"(daddr), "l"(src));
}
#define CP_COMMIT() asm volatile("cp.async.commit_group;" ::: "memory")
#define CP_WAIT0()  asm volatile("cp.async.wait_group 0;" ::: "memory")

// ---------------------------------------------------------------------------
// Kernel 1: x [B,C,H,W] -> xT [B,H,W,C]
// ---------------------------------------------------------------------------
__global__ void xpose_kernel(const float* __restrict__ x) {
    __shared__ float tile[32][33];
    int b   = blockIdx.z;
    int hw0 = blockIdx.x * 32;
    int c0  = blockIdx.y * 32;
    const float* xb = x + (size_t)b * CC * HW;
#pragma unroll
    for (int j = 0; j < 32; j += 8)
        tile[threadIdx.y + j][threadIdx.x] =
            xb[(size_t)(c0 + threadIdx.y + j) * HW + hw0 + threadIdx.x];
    __syncthreads();
    float* ob = g_xT + (size_t)b * HW * CC;
#pragma unroll
    for (int j = 0; j < 32; j += 8)
        ob[(size_t)(hw0 + threadIdx.y + j) * CC + c0 + threadIdx.x] =
            tile[threadIdx.x][threadIdx.y + j];
}

// ---------------------------------------------------------------------------
// Kernel 2: weight [O,C,3,3] -> per-chunk bf16 hi/lo B tiles [ch][o(128)][c(64)]
// chunk ch: tap k = ch/2, channels c in [(ch&1)*64, +64)
// ---------------------------------------------------------------------------
__global__ void wprep_kernel(const float* __restrict__ w) {
    int idx = blockIdx.x * blockDim.x + threadIdx.x;
    if (idx >= NCHUNK * 128 * 64) return;
    int c  = idx & 63;
    int o  = (idx >> 6) & 127;
    int ch = idx >> 13;
    int k  = ch >> 1;
    int cf = ((ch & 1) << 6) + c;
    float v = w[(size_t)o * CK + cf * KTAP + k];
    __nv_bfloat16 hi = __float2bfloat16(v);
    __nv_bfloat16 lo = __float2bfloat16(v - __bfloat162float(hi));
    size_t off = (size_t)ch * 16384 + o * 128 + c * 2;
    *reinterpret_cast<__nv_bfloat16*>(g_wbHi + off) = hi;
    *reinterpret_cast<__nv_bfloat16*>(g_wbLo + off) = lo;
}

// ---------------------------------------------------------------------------
// Kernel 3: fused gather + mma.sync bf16-split GEMM
// grid = 256 (one CTA per 128 spatial positions of one batch), 256 threads
// ---------------------------------------------------------------------------
__global__ void __launch_bounds__(256, 1) dcn_mma_kernel(
    const float* __restrict__ offset,
    const float* __restrict__ bias,
    float* __restrict__ out)
{
    extern __shared__ char smem[];
    const uint32_t sb = smem_u32(smem);
    const int tid  = threadIdx.x;
    const int wid  = tid >> 5;
    const int lane = tid & 31;
    const int b    = blockIdx.x >> 5;
    const int ho0  = (blockIdx.x & 31) * 2;
    const int hw0  = (blockIdx.x & 31) * 128;

    int*   sIdx = reinterpret_cast<int*>(smem + SM_IDX);
    float* sWt  = reinterpret_cast<float*>(smem + SM_WT);

    // ---- precompute bilinear params for all (tap, m) ----
    for (int p = tid; p < KTAP * 128; p += 256) {
        int m = p & 127;
        int k = p >> 7;
        int ho = ho0 + (m >> 6), wo = m & 63;
        float dy = offset[(((size_t)b * 18 + 2 * k    ) * 64 + ho) * 64 + wo];
        float dx = offset[(((size_t)b * 18 + 2 * k + 1) * 64 + ho) * 64 + wo];
        float py = (float)(ho - 1 + k / 3) + dy;
        float px = (float)(wo - 1 + k % 3) + dx;
        float y0f = floorf(py), x0f = floorf(px);
        int   y0 = (int)y0f,    x0 = (int)x0f;
        float ly = py - y0f, lx = px - x0f;
        float w4[4] = { (1.f - ly) * (1.f - lx), (1.f - ly) * lx,
                        ly * (1.f - lx),         ly * lx };
#pragma unroll
        for (int i = 0; i < 4; i++) {
            int yy = y0 + (i >> 1);
            int xx = x0 + (i & 1);
            bool v = (yy >= 0) & (yy < HH) & (xx >= 0) & (xx < WW);
            sWt[p * 4 + i]  = v ? w4[i] : 0.f;
            sIdx[p * 4 + i] = v ? (((b * HH + yy) * WW + xx) * CC) : 0;
        }
    }
    __syncthreads();

    // ---- helpers as lambdas ----
    auto cpasyncB = [&](int st, int ch) {
        const char* srcH = (const char*)g_wbHi + (size_t)ch * 16384;
        const char* srcL = (const char*)g_wbLo + (size_t)ch * 16384;
        uint32_t dH = sb + B_OFF(st, 0);
        uint32_t dL = sb + B_OFF(st, 1);
#pragma unroll
        for (int i = 0; i < 4; i++) {          // 1024 x 16B segments = 16 KB per half
            int seg = tid + i * 256;           // 0..1023
            int row = seg >> 3, s8 = seg & 7;  // row 0..127
            cp16(dH + row * AROW + s8 * 16, srcH + seg * 16);
            cp16(dL + row * AROW + s8 * 16, srcL + seg * 16);
        }
    };

    auto gatherA = [&](int st, int ch) {
        const int k   = ch >> 1;
        const int gc0 = (ch & 1) << 6;
        const int m   = tid >> 1;
        const int ch0 = (tid & 1) << 5;
        const int4   id = *reinterpret_cast<const int4*>(sIdx + ((k << 7) + m) * 4);
        const float4 wt = *reinterpret_cast<const float4*>(sWt + ((k << 7) + m) * 4);
        char* rowHi = smem + A_OFF(st, 0) + m * AROW;
        char* rowLo = smem + A_OFF(st, 1) + m * AROW;
#pragma unroll
        for (int it = 0; it < 8; it++) {
            int c  = ch0 + (it << 2);
            int cc = gc0 + c;
            float4 a0 = *reinterpret_cast<const float4*>(g_xT + id.x + cc);
            float4 a1 = *reinterpret_cast<const float4*>(g_xT + id.y + cc);
            float4 a2 = *reinterpret_cast<const float4*>(g_xT + id.z + cc);
            float4 a3 = *reinterpret_cast<const float4*>(g_xT + id.w + cc);
            float v0 = wt.x * a0.x + wt.y * a1.x + wt.z * a2.x + wt.w * a3.x;
            float v1 = wt.x * a0.y + wt.y * a1.y + wt.z * a2.y + wt.w * a3.y;
            float v2 = wt.x * a0.z + wt.y * a1.z + wt.z * a2.z + wt.w * a3.z;
            float v3 = wt.x * a0.w + wt.y * a1.w + wt.z * a2.w + wt.w * a3.w;
            __nv_bfloat162 H01 = __floats2bfloat162_rn(v0, v1);
            __nv_bfloat162 H23 = __floats2bfloat162_rn(v2, v3);
            float2 f01 = __bfloat1622float2(H01);
            float2 f23 = __bfloat1622float2(H23);
            __nv_bfloat162 L01 = __floats2bfloat162_rn(v0 - f01.x, v1 - f01.y);
            __nv_bfloat162 L23 = __floats2bfloat162_rn(v2 - f23.x, v3 - f23.y);
            *reinterpret_cast<uint2*>(rowHi + c * 2) =
                make_uint2(*reinterpret_cast<uint32_t*>(&H01), *reinterpret_cast<uint32_t*>(&H23));
            *reinterpret_cast<uint2*>(rowLo + c * 2) =
                make_uint2(*reinterpret_cast<uint32_t*>(&L01), *reinterpret_cast<uint32_t*>(&L23));
        }
    };

    const int mbase = (wid >> 1) * 32;
    const int n0    = (wid & 1) * 64;
    float acc[2][8][4];
#pragma unroll
    for (int i = 0; i < 2; i++)
#pragma unroll
        for (int j = 0; j < 8; j++)
#pragma unroll
            for (int q = 0; q < 4; q++) acc[i][j][q] = 0.f;

    auto mma_chunk = [&](int st) {
        const uint32_t aHi = sb + A_OFF(st, 0), aLo = sb + A_OFF(st, 1);
        const uint32_t bHi = sb + B_OFF(st, 0), bLo = sb + B_OFF(st, 1);
        const uint32_t aoff = (uint32_t)(lane & 15) * AROW + ((uint32_t)(lane >> 4) << 4);
        const uint32_t boff = (uint32_t)(n0 + ((lane >> 4) << 3) + (lane & 7)) * AROW
                            + (((uint32_t)(lane >> 3) & 1) << 4);
#pragma unroll
        for (int s = 0; s < 4; s++) {
            uint32_t Ah[2][4], Al[2][4], Bh[4][4], Bl[4][4];
#pragma unroll
            for (int mt = 0; mt < 2; mt++) {
                ldsm4(aHi + aoff + (mbase + mt * 16) * AROW + s * 32, Ah[mt]);
                ldsm4(aLo + aoff + (mbase + mt * 16) * AROW + s * 32, Al[mt]);
            }
#pragma unroll
            for (int p = 0; p < 4; p++) {
                ldsm4(bHi + boff + p * 16 * AROW + s * 32, Bh[p]);
                ldsm4(bLo + boff + p * 16 * AROW + s * 32, Bl[p]);
            }
#pragma unroll
            for (int mt = 0; mt < 2; mt++)
#pragma unroll
                for (int p = 0; p < 4; p++) {
                    mma16816(acc[mt][p * 2],     Ah[mt], &Bh[p][0]);
                    mma16816(acc[mt][p * 2 + 1], Ah[mt], &Bh[p][2]);
                }
#pragma unroll
            for (int mt = 0; mt < 2; mt++)
#pragma unroll
                for (int p = 0; p < 4; p++) {
                    mma16816(acc[mt][p * 2],     Ah[mt], &Bl[p][0]);
                    mma16816(acc[mt][p * 2 + 1], Ah[mt], &Bl[p][2]);
                }
#pragma unroll
            for (int mt = 0; mt < 2; mt++)
#pragma unroll
                for (int p = 0; p < 4; p++) {
                    mma16816(acc[mt][p * 2],     Al[mt], &Bh[p][0]);
                    mma16816(acc[mt][p * 2 + 1], Al[mt], &Bh[p][2]);
                }
        }
    };

    // ---- prologue: fill stage 0 ----
    cpasyncB(0, 0);
    CP_COMMIT();
    gatherA(0, 0);
    CP_WAIT0();
    __syncthreads();

    // ---- main loop, double-buffered; SMSP-partner warps alternate order ----
    const bool gfirst = (wid >> 2) & 1;     // warps 4-7 gather first (partner of 0-3 per SMSP)
    for (int ch = 0; ch < NCHUNK; ch++) {
        int cur = ch & 1, nxt = cur ^ 1;
        if (ch + 1 < NCHUNK) { cpasyncB(nxt, ch + 1); CP_COMMIT(); }
        if (gfirst) {
            if (ch + 1 < NCHUNK) gatherA(nxt, ch + 1);
            mma_chunk(cur);
        } else {
            mma_chunk(cur);
            if (ch + 1 < NCHUNK) gatherA(nxt, ch + 1);
        }
        CP_WAIT0();
        __syncthreads();
    }

    // ---- epilogue: write 32x64 per warp, add bias ----
#pragma unroll
    for (int nt = 0; nt < 8; nt++) {
        int n = n0 + nt * 8 + (lane & 3) * 2;
        float bv0 = __ldg(bias + n);
        float bv1 = __ldg(bias + n + 1);
        float* o0 = out + ((size_t)b * OO + n) * HW + hw0;
        float* o1 = o0 + HW;
#pragma unroll
        for (int mt = 0; mt < 2; mt++) {
            int mr = mbase + mt * 16 + (lane >> 2);
            o0[mr]     = acc[mt][nt][0] + bv0;
            o1[mr]     = acc[mt][nt][1] + bv1;
            o0[mr + 8] = acc[mt][nt][2] + bv0;
            o1[mr + 8] = acc[mt][nt][3] + bv1;
        }
    }
}

// ---------------------------------------------------------------------------
extern "C" void kernel_launch(void* const* d_in, const int* in_sizes, int n_in,
                              void* d_out, int out_size)
{
    const float* x      = (const float*)d_in[0];
    const float* offset = (const float*)d_in[1];
    const float* weight = (const float*)d_in[2];
    const float* bias   = (const float*)d_in[3];
    float* out = (float*)d_out;

    cudaFuncSetAttribute(dcn_mma_kernel,
                         cudaFuncAttributeMaxDynamicSharedMemorySize, SMEM_TOTAL);

    dim3 g1(HW / 32, CC / 32, BB), b1(32, 8);
    xpose_kernel<<<g1, b1>>>(x);

    int nw = NCHUNK * 128 * 64;
    wprep_kernel<<<(nw + 255) / 256, 256>>>(weight);

    dcn_mma_kernel<<<256, 256, SMEM_TOTAL>>>(offset, bias, out);
}